// round 4
// baseline (speedup 1.0000x reference)
#include <cuda_runtime.h>
#include <cstdint>

// ---------------------------------------------------------------------------
// R2: batch-paired f32x2 accumulators, k-major activations (natural float2
// pairs, no duplication), pre-duplicated weights ({w,w} float2 built once by a
// prep kernel) so the inner loop is pure LDS + FFMA2 with zero packing MOVs.
// Warp tile 32 cols x 32 batch; lane = 8 pairGroups x 4 colGroups;
// thread = 2 pairs x 8 cols = 16 f32x2 acc. Weights stream via 3-deep
// cp.async ring of 16-row dup tiles.
// ---------------------------------------------------------------------------

typedef unsigned long long ull;

#define THREADS 256
#define TILE_B  32
#define KTROWS  16

__device__ __forceinline__ void fma2(ull& acc, ull a, ull b) {
    asm("fma.rn.f32x2 %0, %1, %2, %0;" : "+l"(acc) : "l"(a), "l"(b));
}
__device__ __forceinline__ void unpack2(ull v, float& lo, float& hi) {
    asm("mov.b64 {%0,%1}, %2;" : "=f"(lo), "=f"(hi) : "l"(v));
}
__device__ __forceinline__ void cp16(uint32_t dst, const void* src) {
    asm volatile("cp.async.cg.shared.global [%0], [%1], 16;" :: "r"(dst), "l"(src));
}

// duplicated weights, built once per graph replay by dup_weights_kernel
__device__ __align__(16) float2 g_w1d[13 * 256];
__device__ __align__(16) float2 g_w2d[256 * 256];
__device__ __align__(16) float2 g_w3d[256 * 256];

__global__ void dup_weights_kernel(const float* __restrict__ w1,
                                   const float* __restrict__ w2,
                                   const float* __restrict__ w3) {
    int i = blockIdx.x * blockDim.x + threadIdx.x;
    if (i < 13 * 256) g_w1d[i] = make_float2(w1[i], w1[i]);
    if (i < 256 * 256) {
        g_w2d[i] = make_float2(w2[i], w2[i]);
        g_w3d[i] = make_float2(w3[i], w3[i]);
    }
}

// SMEM float offsets
#define OFF_WBUF 0        // 3 * 16*512 = 24576   (3 dup weight tiles, 32KB ea)
#define OFF_W1S  24576    // 13*512 = 6656        (dup W1, resident)
#define OFF_ACTA 31232    // 256*32 = 8192        (k-major act, float pairs)
#define OFF_ACTB 39424    // 8192
#define OFF_B1D  47616    // 512 (dup bias)
#define OFF_B2D  48128    // 512
#define OFF_B3D  48640    // 512
#define OFF_WMU  49152    // 512
#define OFF_BMU  49664    // 2 (+6 pad)
#define OFF_OBS  49672    // 13*32 = 416 (k-major obs)
#define OFF_AS   50088    // 64
#define SMEM_FLOATS 50152
#define SMEM_BYTES  (SMEM_FLOATS * 4)   // 200,608 B

// prefetch one 16-row dup weight tile (32KB) into smem buffer
__device__ __forceinline__ void pf_tile(uint32_t wbase, const float2* __restrict__ Wg,
                                        int t, int tx) {
    const float4* src = (const float4*)(Wg + t * KTROWS * 256) + tx;  // 2048 float4 / tile
    uint32_t dst = wbase + tx * 16;
    #pragma unroll
    for (int r = 0; r < 8; r++) cp16(dst + r * 4096, src + r * 256);
    asm volatile("cp.async.commit_group;");
}

__device__ __forceinline__ void bias_init(ull acc[2][4][2], const float* biasD,
                                          int w, int cg) {
    #pragma unroll
    for (int i = 0; i < 4; i++) {
        ulonglong2 bv = *(const ulonglong2*)(biasD + w * 64 + i * 16 + cg * 4);
        acc[0][i][0] = bv.x; acc[0][i][1] = bv.y;
        acc[1][i][0] = bv.x; acc[1][i][1] = bv.y;
    }
}

__device__ __forceinline__ void epilogue_relu(ull acc[2][4][2], float* actOut,
                                              int w, int cg, int gg) {
    #pragma unroll
    for (int p = 0; p < 2; p++)
        #pragma unroll
        for (int i = 0; i < 4; i++)
            #pragma unroll
            for (int u = 0; u < 2; u++) {
                float lo, hi; unpack2(acc[p][i][u], lo, hi);
                lo = fmaxf(lo, 0.f); hi = fmaxf(hi, 0.f);
                int j = w * 32 + i * 8 + cg * 2 + u;
                *(float2*)(actOut + j * 32 + gg * 4 + p * 2) = make_float2(lo, hi);
            }
}

// input layer: obs(13) -> 256, W1 dup resident in smem
__device__ __forceinline__ void layer_in(const float* __restrict__ obsT,
                                         float* __restrict__ actOut,
                                         const float* __restrict__ W1s,
                                         const float* __restrict__ biasD, int tx) {
    const int w = tx >> 5, cg = tx & 3, gg = (tx & 31) >> 2;
    ull acc[2][4][2];
    bias_init(acc, biasD, w, cg);
    #pragma unroll
    for (int k = 0; k < 13; k++) {
        ull a0 = *(const ull*)(obsT + k * 32 + gg * 4);
        ull a1 = *(const ull*)(obsT + k * 32 + gg * 4 + 2);
        #pragma unroll
        for (int i = 0; i < 4; i++) {
            ulonglong2 wv = *(const ulonglong2*)(W1s + k * 512 + w * 64 + i * 16 + cg * 4);
            fma2(acc[0][i][0], a0, wv.x);
            fma2(acc[0][i][1], a0, wv.y);
            fma2(acc[1][i][0], a1, wv.x);
            fma2(acc[1][i][1], a1, wv.y);
        }
    }
    epilogue_relu(acc, actOut, w, cg, gg);
    __syncthreads();
}

// 256 -> 256 layer, weights streamed through a 3-buffer cp.async ring
__device__ __forceinline__ void layer_mid(const float* __restrict__ actIn,
                                          float* __restrict__ actOut,
                                          const float2* __restrict__ Wg,
                                          const float* __restrict__ biasD,
                                          const float* __restrict__ Wbuf,
                                          uint32_t wbufs, int tx, bool pre) {
    const int w = tx >> 5, cg = tx & 3, gg = (tx & 31) >> 2;
    ull acc[2][4][2];
    bias_init(acc, biasD, w, cg);

    if (!pre) {
        pf_tile(wbufs, Wg, 0, tx);
        pf_tile(wbufs + 32768u, Wg, 1, tx);
    }

    #pragma unroll 1
    for (int kt = 0; kt < 16; kt++) {
        if (kt < 15) asm volatile("cp.async.wait_group 1;");
        else         asm volatile("cp.async.wait_group 0;");
        __syncthreads();
        if (kt < 14) pf_tile(wbufs + (uint32_t)((kt + 2) % 3) * 32768u, Wg, kt + 2, tx);

        const float* WT = Wbuf + (kt % 3) * 8192;
        const float* aT = actIn + kt * 512;
        #pragma unroll 4
        for (int kk = 0; kk < 16; kk++) {
            ull a0 = *(const ull*)(aT + kk * 32 + gg * 4);
            ull a1 = *(const ull*)(aT + kk * 32 + gg * 4 + 2);
            #pragma unroll
            for (int i = 0; i < 4; i++) {
                ulonglong2 wv = *(const ulonglong2*)(WT + kk * 512 + w * 64 + i * 16 + cg * 4);
                fma2(acc[0][i][0], a0, wv.x);
                fma2(acc[0][i][1], a0, wv.y);
                fma2(acc[1][i][0], a1, wv.x);
                fma2(acc[1][i][1], a1, wv.y);
            }
        }
    }
    __syncthreads();  // all reads of Wbuf/actIn done before epilogue overwrite patterns
    epilogue_relu(acc, actOut, w, cg, gg);
    __syncthreads();
}

__device__ __forceinline__ void write_obs_T(float* obsT, int b, float px, float py) {
    const float iw = 0.1f;
    obsT[0 * 32 + b] = px * iw;
    obsT[1 * 32 + b] = py * iw;
    obsT[2 * 32 + b] = (4.0f - px) * iw;
    obsT[3 * 32 + b] = (3.0f - py) * iw;
    const float ox[3]  = {1.75f, 1.75f, 3.75f};
    const float oy[3]  = {1.75f, 3.75f, 2.00f};
    const float orr[3] = {0.38f, 0.42f, 0.34f};
    #pragma unroll
    for (int i = 0; i < 3; i++) {
        float dx = px - ox[i], dy = py - oy[i];
        float dist = sqrtf(dx * dx + dy * dy + 1e-9f);
        obsT[(4 + 2 * i) * 32 + b] = -dx * iw;
        obsT[(5 + 2 * i) * 32 + b] = -dy * iw;
        obsT[(10 + i) * 32 + b]    = dist - orr[i];
    }
}

__global__ void __launch_bounds__(THREADS, 1)
rollout_kernel(const float* __restrict__ pos0, const float* __restrict__ wind,
               const float* __restrict__ b1g, const float* __restrict__ b2g,
               const float* __restrict__ b3g, const float* __restrict__ wmu,
               const float* __restrict__ bmug, float* __restrict__ out)
{
    extern __shared__ float sm[];
    float* Wbuf = sm + OFF_WBUF;
    float* W1s  = sm + OFF_W1S;
    float* actA = sm + OFF_ACTA;
    float* actB = sm + OFF_ACTB;
    float* b1d  = sm + OFF_B1D;
    float* b2d  = sm + OFF_B2D;
    float* b3d  = sm + OFF_B3D;
    float* wmuS = sm + OFF_WMU;
    float* bmuS = sm + OFF_BMU;
    float* obsT = sm + OFF_OBS;
    float* aS   = sm + OFF_AS;

    const int tx = threadIdx.x;
    const int b0 = blockIdx.x * TILE_B;
    const uint32_t wbufs = (uint32_t)__cvta_generic_to_shared(Wbuf);

    // stage resident dup W1, dup biases, head weights
    for (int i = tx; i < 3328; i += THREADS) ((float2*)W1s)[i] = g_w1d[i];
    {
        float v;
        v = b1g[tx]; ((float2*)b1d)[tx] = make_float2(v, v);
        v = b2g[tx]; ((float2*)b2d)[tx] = make_float2(v, v);
        v = b3g[tx]; ((float2*)b3d)[tx] = make_float2(v, v);
    }
    for (int i = tx; i < 512; i += THREADS) wmuS[i] = wmu[i];
    if (tx < 2) bmuS[tx] = bmug[tx];

    // per-lane rollout state
    float px = 0.f, py = 0.f, wx = 0.f, wy = 0.f;
    float m_s = -1e30f, s_s = 0.f, m_r = -1e30f, s_r = 0.f;
    if (tx < TILE_B) {
        px = pos0[(b0 + tx) * 2 + 0]; py = pos0[(b0 + tx) * 2 + 1];
        wx = wind[(b0 + tx) * 2 + 0]; wy = wind[(b0 + tx) * 2 + 1];
        write_obs_T(obsT, tx, px, py);
    }
    __syncthreads();

    #pragma unroll 1
    for (int t = 0; t < 64; t++) {
        // start streaming layer-2 weights while layer 1 computes
        pf_tile(wbufs, g_w2d, 0, tx);
        pf_tile(wbufs + 32768u, g_w2d, 1, tx);

        layer_in(obsT, actA, W1s, b1d, tx);
        layer_mid(actA, actB, g_w2d, b2d, Wbuf, wbufs, tx, true);
        layer_mid(actB, actA, g_w3d, b3d, Wbuf, wbufs, tx, false);

        // output head: a = clip(h3 @ wmu + bmu); h3 is k-major in actA
        if (tx < 64) {
            int m = tx & 1, b = tx >> 1;
            float a0 = bmuS[m], a1 = 0.f, a2 = 0.f, a3 = 0.f;
            #pragma unroll 8
            for (int j = 0; j < 256; j += 4) {
                a0 = fmaf(actA[(j + 0) * 32 + b], wmuS[(j + 0) * 2 + m], a0);
                a1 = fmaf(actA[(j + 1) * 32 + b], wmuS[(j + 1) * 2 + m], a1);
                a2 = fmaf(actA[(j + 2) * 32 + b], wmuS[(j + 2) * 2 + m], a2);
                a3 = fmaf(actA[(j + 3) * 32 + b], wmuS[(j + 3) * 2 + m], a3);
            }
            float acc = (a0 + a1) + (a2 + a3);
            aS[b * 2 + m] = fminf(fmaxf(acc, -1.f), 1.f);
        }
        __syncthreads();

        // dynamics + online STREL accumulators + next obs
        if (tx < TILE_B) {
            float vx = 2.f * aS[tx * 2 + 0] + wx;
            float vy = 2.f * aS[tx * 2 + 1] + wy;
            #pragma unroll
            for (int s = 0; s < 4; s++) {
                px = fminf(fmaxf(px + 0.0625f * vx, -4.f), 10.f);
                py = fminf(fmaxf(py + 0.0625f * vy, -4.f), 10.f);
            }
            float dx = px - 1.75f, dy = py - 1.75f;
            float x0 = -50.f * (sqrtf(dx * dx + dy * dy + 1e-9f) - 0.38f);
            dx = px - 1.75f; dy = py - 3.75f;
            float x1 = -50.f * (sqrtf(dx * dx + dy * dy + 1e-9f) - 0.42f);
            dx = px - 3.75f; dy = py - 2.00f;
            float x2 = -50.f * (sqrtf(dx * dx + dy * dy + 1e-9f) - 0.34f);
            float mm = fmaxf(x0, fmaxf(x1, x2));
            float safe = -(mm + logf(expf(x0 - mm) + expf(x1 - mm) + expf(x2 - mm))) * 0.02f;

            float dgx = px - 4.f, dgy = py - 3.f;
            float reach = 0.45f - sqrtf(dgx * dgx + dgy * dgy + 1e-9f);

            float xs = -8.f * safe;
            if (xs > m_s) { s_s = s_s * expf(m_s - xs) + 1.f; m_s = xs; }
            else          { s_s += expf(xs - m_s); }
            float xr = 8.f * reach;
            if (xr > m_r) { s_r = s_r * expf(m_r - xr) + 1.f; m_r = xr; }
            else          { s_r += expf(xr - m_r); }

            write_obs_T(obsT, tx, px, py);
        }
        __syncthreads();
    }

    if (tx < TILE_B) {
        float rho_safe  = -(m_s + logf(s_s)) * 0.125f;
        float rho_reach =  (m_r + logf(s_r)) * 0.125f;
        float u0 = -8.f * rho_safe, u1 = -8.f * rho_reach;
        float mm = fmaxf(u0, u1);
        float rho = -(mm + logf(expf(u0 - mm) + expf(u1 - mm))) * 0.125f;
        out[b0 + tx] = rho;
    }
}

extern "C" void kernel_launch(void* const* d_in, const int* in_sizes, int n_in,
                              void* d_out, int out_size) {
    const float* pos0 = (const float*)d_in[0];
    const float* wind = (const float*)d_in[1];
    const float* w1   = (const float*)d_in[2];
    const float* b1   = (const float*)d_in[3];
    const float* w2   = (const float*)d_in[4];
    const float* b2   = (const float*)d_in[5];
    const float* w3   = (const float*)d_in[6];
    const float* b3   = (const float*)d_in[7];
    const float* wmu  = (const float*)d_in[8];
    const float* bmu  = (const float*)d_in[9];
    float* out = (float*)d_out;

    dup_weights_kernel<<<256, 256>>>(w1, w2, w3);

    cudaFuncSetAttribute(rollout_kernel,
                         cudaFuncAttributeMaxDynamicSharedMemorySize, SMEM_BYTES);
    int grid = out_size / TILE_B;  // 1024
    rollout_kernel<<<grid, THREADS, SMEM_BYTES>>>(pos0, wind, b1, b2, b3,
                                                  wmu, bmu, out);
}

// round 11
// speedup vs baseline: 4.8385x; 4.8385x over previous
#include <cuda_runtime.h>
#include <cuda_bf16.h>
#include <cstdint>

// ---------------------------------------------------------------------------
// R6: warp-level HMMA (mma.sync bf16, base PTX -> compiles at compute_103).
// 256 CTAs x 128 batch, 8 warps; warp owns 16 rows x all 256 cols.
// Split-bf16 3-term: Ahi*Whi + Ahi*Wlo + Alo*Whi, fp32 accum.
// A (act) in SMEM as bf16 hi/lo 8x8 tiles (stmatrix out / ldmatrix in),
// warp-private rows -> no inter-layer barriers. W1 resident; W2/W3 streamed
// as 16 x 32KB k-chunks via 2-slot cp.async ring with DEPTH-1 prefetch
// (chunk c+1 issued at iteration c -> never writes the slot being read;
// R5's c+2 prefetch raced with the compute slot and corrupted weights).
// Head via in-register dot + shfl butterflies; dynamics/STREL per-thread.
// ---------------------------------------------------------------------------

#define THREADS 256
#define TILE_B  128

// SMEM byte offsets
#define A_HI   0u        // 8 warps x 16 kt16 x 4 tiles x 128B = 65536
#define A_LO   65536u
#define RING   131072u   // 2 x 32768
#define W1I    196608u   // 16384 (hi 8192 | lo 8192)
#define BIAS1  212992u
#define BIAS2  214016u
#define BIAS3  215040u
#define WMUO   216064u   // 512 floats
#define BMUO   218112u   // 2 floats
#define ASO    218120u   // 128 x float2
#define SMEM_BYTES 219144u

// ============================ PTX helpers ===================================
__device__ __forceinline__ uint32_t smem_to_u32(const void* p) {
    uint32_t a;
    asm("{ .reg .u64 t; cvta.to.shared.u64 t, %1; cvt.u32.u64 %0, t; }"
        : "=r"(a) : "l"(p));
    return a;
}
__device__ __forceinline__ void cp16(uint32_t dst, const void* src) {
    asm volatile("cp.async.cg.shared.global [%0], [%1], 16;" :: "r"(dst), "l"(src));
}
#define CP_COMMIT() asm volatile("cp.async.commit_group;")

__device__ __forceinline__ void ldsm4(uint32_t& r0, uint32_t& r1, uint32_t& r2,
                                      uint32_t& r3, uint32_t addr) {
    asm volatile("ldmatrix.sync.aligned.m8n8.x4.shared.b16 {%0,%1,%2,%3}, [%4];"
                 : "=r"(r0), "=r"(r1), "=r"(r2), "=r"(r3) : "r"(addr));
}
__device__ __forceinline__ void stsm4(uint32_t addr, uint32_t r0, uint32_t r1,
                                      uint32_t r2, uint32_t r3) {
    asm volatile("stmatrix.sync.aligned.m8n8.x4.shared.b16 [%0], {%1,%2,%3,%4};"
                 :: "r"(addr), "r"(r0), "r"(r1), "r"(r2), "r"(r3) : "memory");
}
__device__ __forceinline__ void mma16816(float* c, uint32_t a0, uint32_t a1,
                                         uint32_t a2, uint32_t a3,
                                         uint32_t b0, uint32_t b1) {
    asm volatile("mma.sync.aligned.m16n8k16.row.col.f32.bf16.bf16.f32 "
                 "{%0,%1,%2,%3}, {%4,%5,%6,%7}, {%8,%9}, {%0,%1,%2,%3};"
                 : "+f"(c[0]), "+f"(c[1]), "+f"(c[2]), "+f"(c[3])
                 : "r"(a0), "r"(a1), "r"(a2), "r"(a3), "r"(b0), "r"(b1));
}

__device__ __forceinline__ void split2(float v0, float v1, uint32_t& hw, uint32_t& lw) {
    __nv_bfloat162 h = __floats2bfloat162_rn(v0, v1);
    hw = *reinterpret_cast<uint32_t*>(&h);
    float r0 = v0 - __bfloat162float(h.x);
    float r1 = v1 - __bfloat162float(h.y);
    __nv_bfloat162 l = __floats2bfloat162_rn(r0, r1);
    lw = *reinterpret_cast<uint32_t*>(&l);
}

// ===================== pre-tiled weight images ==============================
// 8x8 bf16 tiles, transposed within tile (T[r][c] = W[k0+c][n0+r]) so plain
// ldmatrix yields mma.sync B fragments. Chunk (k32): hi 16KB | lo 16KB;
// group (kt16l, npair) = 4 tiles {(k8=0,n8=0),(1,0),(0,1),(1,1)} = 512B.
__device__ __align__(16) unsigned char g_w1img[16384];
__device__ __align__(16) unsigned char g_w2img[8][32768];
__device__ __align__(16) unsigned char g_w3img[8][32768];

__global__ void prep_kernel(const float* __restrict__ w1,
                            const float* __restrict__ w2,
                            const float* __restrict__ w3) {
    int i = blockIdx.x * blockDim.x + threadIdx.x;   // 65536 = k(256) x n(256)
    int k = i >> 8, n = i & 255;
    int c = k >> 5, kt16l = (k >> 4) & 1, kt8 = (k >> 3) & 1;
    int npair = n >> 4, ntp = (n >> 3) & 1;
    int r = n & 7, cc = k & 7;
    int off = (kt16l * 16 + npair) * 512 + (ntp * 2 + kt8) * 128 + r * 16 + cc * 2;
    {
        float v = w2[k * 256 + n];
        __nv_bfloat16 h = __float2bfloat16(v);
        __nv_bfloat16 l = __float2bfloat16(v - __bfloat162float(h));
        *(__nv_bfloat16*)(g_w2img[c] + off) = h;
        *(__nv_bfloat16*)(g_w2img[c] + 16384 + off) = l;
    }
    {
        float v = w3[k * 256 + n];
        __nv_bfloat16 h = __float2bfloat16(v);
        __nv_bfloat16 l = __float2bfloat16(v - __bfloat162float(h));
        *(__nv_bfloat16*)(g_w3img[c] + off) = h;
        *(__nv_bfloat16*)(g_w3img[c] + 16384 + off) = l;
    }
    if (k < 16) {   // W1: K padded 13 -> 16 with zeros
        float v = (k < 13) ? w1[k * 256 + n] : 0.0f;
        __nv_bfloat16 h = __float2bfloat16(v);
        __nv_bfloat16 l = __float2bfloat16(v - __bfloat162float(h));
        int o1 = npair * 512 + (ntp * 2 + kt8) * 128 + r * 16 + cc * 2;
        *(__nv_bfloat16*)(g_w1img + o1) = h;
        *(__nv_bfloat16*)(g_w1img + 8192 + o1) = l;
    }
}

// ================================ kernel ====================================
__global__ void __launch_bounds__(THREADS, 1)
rollout_kernel(const float* __restrict__ pos0, const float* __restrict__ wind,
               const float* __restrict__ b1g, const float* __restrict__ b2g,
               const float* __restrict__ b3g, const float* __restrict__ wmu,
               const float* __restrict__ bmug, float* __restrict__ out)
{
    extern __shared__ __align__(128) unsigned char smem[];
    const uint32_t smb = smem_to_u32(smem);
    float* bias1 = (float*)(smem + BIAS1);
    float* bias2 = (float*)(smem + BIAS2);
    float* bias3 = (float*)(smem + BIAS3);
    float* wmuS  = (float*)(smem + WMUO);
    float* bmuS  = (float*)(smem + BMUO);
    float2* aS   = (float2*)(smem + ASO);

    const int tid = threadIdx.x;
    const int w   = tid >> 5;
    const int l   = tid & 31;
    const int b0  = blockIdx.x * TILE_B;
    const uint32_t lofs = (uint32_t)l * 16u;
    const int cb = 2 * (l & 3);                 // col offset within 8-col tile

    // stage W1 image (16KB) + biases + head weights
    {
        const unsigned char* src = g_w1img + tid * 16;
        uint32_t dst = smb + W1I + tid * 16;
        #pragma unroll
        for (int r = 0; r < 4; r++) cp16(dst + r * 4096, src + r * 4096);
        CP_COMMIT();
        bias1[tid] = b1g[tid]; bias2[tid] = b2g[tid]; bias3[tid] = b3g[tid];
        wmuS[tid] = wmu[tid]; wmuS[256 + tid] = wmu[256 + tid];
        if (tid < 2) bmuS[tid] = bmug[tid];
        asm volatile("cp.async.wait_group 0;");
    }

    // per-thread rollout state (threads 0..127 own one batch row each)
    float px = 0.f, py = 0.f, wx = 0.f, wy = 0.f;
    float m_s = -1e30f, s_s = 0.f, m_r = -1e30f, s_r = 0.f;
    const float ox[3]  = {1.75f, 1.75f, 3.75f};
    const float oy[3]  = {1.75f, 3.75f, 2.00f};
    const float orr[3] = {0.38f, 0.42f, 0.34f};

    if (tid < TILE_B) {
        px = pos0[(b0 + tid) * 2 + 0]; py = pos0[(b0 + tid) * 2 + 1];
        wx = wind[(b0 + tid) * 2 + 0]; wy = wind[(b0 + tid) * 2 + 1];
    }

    // obs writer: thread tid (row b) -> A tiles, kt16=0, 16 cols (3 zero pad)
    auto write_obs = [&](int b, float lpx, float lpy) {
        float o[16];
        o[0] = lpx * 0.1f; o[1] = lpy * 0.1f;
        o[2] = (4.0f - lpx) * 0.1f; o[3] = (3.0f - lpy) * 0.1f;
        #pragma unroll
        for (int i = 0; i < 3; i++) {
            float dx = lpx - ox[i], dy = lpy - oy[i];
            float dist = sqrtf(dx * dx + dy * dy + 1e-9f);
            o[4 + 2 * i] = -dx * 0.1f;
            o[5 + 2 * i] = -dy * 0.1f;
            o[10 + i]    = dist - orr[i];
        }
        o[13] = 0.f; o[14] = 0.f; o[15] = 0.f;
        uint32_t base = (uint32_t)(b >> 4) * 8192u + (uint32_t)((b >> 3) & 1) * 128u
                      + (uint32_t)(b & 7) * 16u;
        #pragma unroll
        for (int k = 0; k < 16; k++) {
            uint32_t a = base + (uint32_t)(k >> 3) * 256u + (uint32_t)(k & 7) * 2u;
            __nv_bfloat16 h = __float2bfloat16(o[k]);
            __nv_bfloat16 lo = __float2bfloat16(o[k] - __bfloat162float(h));
            *(__nv_bfloat16*)(smem + A_HI + a) = h;
            *(__nv_bfloat16*)(smem + A_LO + a) = lo;
        }
    };

    if (tid < TILE_B) write_obs(tid, px, py);
    __syncthreads();

    const uint32_t aHiW = smb + A_HI + (uint32_t)w * 8192u + lofs;
    const uint32_t w1b  = smb + W1I + lofs;

    float C[32][4];
    #pragma unroll
    for (int t = 0; t < 32; t++) { C[t][0] = 0.f; C[t][1] = 0.f; C[t][2] = 0.f; C[t][3] = 0.f; }

    // epilogue: C + bias -> relu -> bf16 hi/lo -> stmatrix into A; reset C
    auto store_act = [&](const float* bias) {
        #pragma unroll
        for (int np = 0; np < 16; np++) {
            int t0 = 2 * np, t1 = t0 + 1;
            float2 bb0 = *(const float2*)(bias + 8 * t0 + cb);
            float2 bb1 = *(const float2*)(bias + 8 * t1 + cb);
            float v00 = fmaxf(C[t0][0] + bb0.x, 0.f), v01 = fmaxf(C[t0][1] + bb0.y, 0.f);
            float v02 = fmaxf(C[t0][2] + bb0.x, 0.f), v03 = fmaxf(C[t0][3] + bb0.y, 0.f);
            float v10 = fmaxf(C[t1][0] + bb1.x, 0.f), v11 = fmaxf(C[t1][1] + bb1.y, 0.f);
            float v12 = fmaxf(C[t1][2] + bb1.x, 0.f), v13 = fmaxf(C[t1][3] + bb1.y, 0.f);
            uint32_t m0h, m0l, m1h, m1l, m2h, m2l, m3h, m3l;
            split2(v00, v01, m0h, m0l); split2(v02, v03, m1h, m1l);
            split2(v10, v11, m2h, m2l); split2(v12, v13, m3h, m3l);
            uint32_t adr = aHiW + (uint32_t)np * 512u;
            stsm4(adr, m0h, m1h, m2h, m3h);
            stsm4(adr + 65536u, m0l, m1l, m2l, m3l);
            C[t0][0] = 0.f; C[t0][1] = 0.f; C[t0][2] = 0.f; C[t0][3] = 0.f;
            C[t1][0] = 0.f; C[t1][1] = 0.f; C[t1][2] = 0.f; C[t1][3] = 0.f;
        }
        __syncwarp();
    };

    #pragma unroll 1
    for (int t = 0; t < 64; t++) {
        // prefetch FIRST W2 chunk only (depth-1 ring; slot 0 free by step-end barriers)
        {
            const unsigned char* s0 = g_w2img[0] + tid * 16;
            uint32_t d0 = smb + RING + tid * 16;
            #pragma unroll
            for (int r = 0; r < 8; r++) cp16(d0 + r * 4096, s0 + r * 4096);
            CP_COMMIT();
        }

        // ---- layer 1: obs(16) -> 256, W1 resident ----
        {
            uint32_t ah0, ah1, ah2, ah3, al0, al1, al2, al3;
            ldsm4(ah0, ah1, ah2, ah3, aHiW);
            ldsm4(al0, al1, al2, al3, aHiW + 65536u);
            #pragma unroll
            for (int np = 0; np < 16; np++) {
                uint32_t wh0, wh1, wh2, wh3, wl0, wl1, wl2, wl3;
                uint32_t wa = w1b + (uint32_t)np * 512u;
                ldsm4(wh0, wh1, wh2, wh3, wa);
                ldsm4(wl0, wl1, wl2, wl3, wa + 8192u);
                mma16816(C[2 * np],     ah0, ah1, ah2, ah3, wh0, wh1);
                mma16816(C[2 * np + 1], ah0, ah1, ah2, ah3, wh2, wh3);
                mma16816(C[2 * np],     ah0, ah1, ah2, ah3, wl0, wl1);
                mma16816(C[2 * np + 1], ah0, ah1, ah2, ah3, wl2, wl3);
                mma16816(C[2 * np],     al0, al1, al2, al3, wh0, wh1);
                mma16816(C[2 * np + 1], al0, al1, al2, al3, wh2, wh3);
            }
            store_act(bias1);
        }

        // ---- unified 16-chunk stream: chunks 0-7 = W2, 8-15 = W3 ----
        // depth-1: at iteration c, chunk c is resident (waited), chunk c+1 is
        // issued into the OTHER slot (its old contents, chunk c-1, were
        // consumed before this iteration's barrier). No write/read overlap.
        #pragma unroll 1
        for (int c = 0; c < 16; c++) {
            asm volatile("cp.async.wait_group 0;");
            __syncthreads();
            if (c < 15) {
                int nc = c + 1;
                const unsigned char* src =
                    ((nc < 8) ? g_w2img[nc] : g_w3img[nc - 8]) + tid * 16;
                uint32_t dst = smb + RING + (uint32_t)(nc & 1) * 32768u + tid * 16;
                #pragma unroll
                for (int r = 0; r < 8; r++) cp16(dst + r * 4096, src + r * 4096);
                CP_COMMIT();
            }
            uint32_t wslot = smb + RING + (uint32_t)(c & 1) * 32768u + lofs;
            int kl16 = (c & 7) * 2;
            #pragma unroll
            for (int j = 0; j < 2; j++) {
                uint32_t aa = aHiW + (uint32_t)(kl16 + j) * 512u;
                uint32_t ah0, ah1, ah2, ah3, al0, al1, al2, al3;
                ldsm4(ah0, ah1, ah2, ah3, aa);
                ldsm4(al0, al1, al2, al3, aa + 65536u);
                uint32_t wgb = wslot + (uint32_t)j * 8192u;
                #pragma unroll
                for (int np = 0; np < 16; np++) {
                    uint32_t wh0, wh1, wh2, wh3, wl0, wl1, wl2, wl3;
                    uint32_t wa = wgb + (uint32_t)np * 512u;
                    ldsm4(wh0, wh1, wh2, wh3, wa);
                    ldsm4(wl0, wl1, wl2, wl3, wa + 16384u);
                    mma16816(C[2 * np],     ah0, ah1, ah2, ah3, wh0, wh1);
                    mma16816(C[2 * np + 1], ah0, ah1, ah2, ah3, wh2, wh3);
                    mma16816(C[2 * np],     ah0, ah1, ah2, ah3, wl0, wl1);
                    mma16816(C[2 * np + 1], ah0, ah1, ah2, ah3, wl2, wl3);
                    mma16816(C[2 * np],     al0, al1, al2, al3, wh0, wh1);
                    mma16816(C[2 * np + 1], al0, al1, al2, al3, wh2, wh3);
                }
            }
            if (c == 7) store_act(bias2);   // layer-2 epilogue (warp-private A)
        }

        // ---- head: a = h3 @ wmu (bias3+relu in-register), butterfly reduce ----
        {
            float pa0 = 0.f, pa1 = 0.f, pb0 = 0.f, pb1 = 0.f;
            #pragma unroll
            for (int tt = 0; tt < 32; tt++) {
                float2 bb = *(const float2*)(bias3 + 8 * tt + cb);
                float4 f  = *(const float4*)(wmuS + (8 * tt + cb) * 2);
                float v0 = fmaxf(C[tt][0] + bb.x, 0.f);
                float v1 = fmaxf(C[tt][1] + bb.y, 0.f);
                float v2 = fmaxf(C[tt][2] + bb.x, 0.f);
                float v3 = fmaxf(C[tt][3] + bb.y, 0.f);
                pa0 = fmaf(v0, f.x, fmaf(v1, f.z, pa0));
                pa1 = fmaf(v0, f.y, fmaf(v1, f.w, pa1));
                pb0 = fmaf(v2, f.x, fmaf(v3, f.z, pb0));
                pb1 = fmaf(v2, f.y, fmaf(v3, f.w, pb1));
                C[tt][0] = 0.f; C[tt][1] = 0.f; C[tt][2] = 0.f; C[tt][3] = 0.f;
            }
            #pragma unroll
            for (int off = 1; off <= 2; off <<= 1) {
                pa0 += __shfl_xor_sync(0xffffffffu, pa0, off);
                pa1 += __shfl_xor_sync(0xffffffffu, pa1, off);
                pb0 += __shfl_xor_sync(0xffffffffu, pb0, off);
                pb1 += __shfl_xor_sync(0xffffffffu, pb1, off);
            }
            if ((l & 3) == 0) {
                int row = w * 16 + (l >> 2);
                aS[row]     = make_float2(pa0, pa1);
                aS[row + 8] = make_float2(pb0, pb1);
            }
        }
        __syncthreads();

        // ---- dynamics + STREL + next obs (threads 0..127) ----
        if (tid < TILE_B) {
            float2 av = aS[tid];
            float a0 = fminf(fmaxf(av.x + bmuS[0], -1.f), 1.f);
            float a1 = fminf(fmaxf(av.y + bmuS[1], -1.f), 1.f);
            float vx = 2.f * a0 + wx, vy = 2.f * a1 + wy;
            #pragma unroll
            for (int s = 0; s < 4; s++) {
                px = fminf(fmaxf(px + 0.0625f * vx, -4.f), 10.f);
                py = fminf(fmaxf(py + 0.0625f * vy, -4.f), 10.f);
            }
            float dx = px - 1.75f, dy = py - 1.75f;
            float x0 = -50.f * (sqrtf(dx * dx + dy * dy + 1e-9f) - 0.38f);
            dx = px - 1.75f; dy = py - 3.75f;
            float x1 = -50.f * (sqrtf(dx * dx + dy * dy + 1e-9f) - 0.42f);
            dx = px - 3.75f; dy = py - 2.00f;
            float x2 = -50.f * (sqrtf(dx * dx + dy * dy + 1e-9f) - 0.34f);
            float mm = fmaxf(x0, fmaxf(x1, x2));
            float safe = -(mm + logf(expf(x0 - mm) + expf(x1 - mm) + expf(x2 - mm))) * 0.02f;

            float dgx = px - 4.f, dgy = py - 3.f;
            float reach = 0.45f - sqrtf(dgx * dgx + dgy * dgy + 1e-9f);

            float xs = -8.f * safe;
            if (xs > m_s) { s_s = s_s * expf(m_s - xs) + 1.f; m_s = xs; }
            else          { s_s += expf(xs - m_s); }
            float xr = 8.f * reach;
            if (xr > m_r) { s_r = s_r * expf(m_r - xr) + 1.f; m_r = xr; }
            else          { s_r += expf(xr - m_r); }

            write_obs(tid, px, py);
        }
        __syncthreads();
    }

    if (tid < TILE_B) {
        float rho_safe  = -(m_s + logf(s_s)) * 0.125f;
        float rho_reach =  (m_r + logf(s_r)) * 0.125f;
        float u0 = -8.f * rho_safe, u1 = -8.f * rho_reach;
        float mm = fmaxf(u0, u1);
        float rho = -(mm + logf(expf(u0 - mm) + expf(u1 - mm))) * 0.125f;
        out[b0 + tid] = rho;
    }
}

extern "C" void kernel_launch(void* const* d_in, const int* in_sizes, int n_in,
                              void* d_out, int out_size) {
    const float* pos0 = (const float*)d_in[0];
    const float* wind = (const float*)d_in[1];
    const float* w1   = (const float*)d_in[2];
    const float* b1   = (const float*)d_in[3];
    const float* w2   = (const float*)d_in[4];
    const float* b2   = (const float*)d_in[5];
    const float* w3   = (const float*)d_in[6];
    const float* b3   = (const float*)d_in[7];
    const float* wmu  = (const float*)d_in[8];
    const float* bmu  = (const float*)d_in[9];
    float* out = (float*)d_out;

    prep_kernel<<<256, 256>>>(w1, w2, w3);

    cudaFuncSetAttribute(rollout_kernel,
                         cudaFuncAttributeMaxDynamicSharedMemorySize, SMEM_BYTES);
    int grid = out_size / TILE_B;  // 32768/128 = 256
    rollout_kernel<<<grid, THREADS, SMEM_BYTES>>>(pos0, wind, b1, b2, b3,
                                                  wmu, bmu, out);
}